// round 1
// baseline (speedup 1.0000x reference)
#include <cuda_runtime.h>
#include <math.h>

#define BB 4
#define SS 2048
#define DD 1024
#define BSR (BB * SS)          // 8192 rows of Q/K/V
#define SCALE (1.0f / 32.0f)   // BETA / sqrt(D) = 1/32

// Scratch: Q, K, V projections (each 8192 x 1024 fp32 = 32 MB)
__device__ float g_Q[BSR * DD];
__device__ float g_K[BSR * DD];
__device__ float g_V[BSR * DD];

// ---------------------------------------------------------------------------
// Block reductions (256 threads, 8 warps)
// ---------------------------------------------------------------------------
__device__ __forceinline__ float block_reduce_sum(float v, float* sred) {
    #pragma unroll
    for (int o = 16; o > 0; o >>= 1) v += __shfl_xor_sync(0xffffffffu, v, o);
    int wid = threadIdx.x >> 5, lane = threadIdx.x & 31;
    if (lane == 0) sred[wid] = v;
    __syncthreads();
    if (wid == 0) {
        float t = (lane < 8) ? sred[lane] : 0.0f;
        #pragma unroll
        for (int o = 4; o > 0; o >>= 1) t += __shfl_xor_sync(0xffffffffu, t, o);
        if (lane == 0) sred[0] = t;
    }
    __syncthreads();
    float r = sred[0];
    __syncthreads();
    return r;
}

__device__ __forceinline__ float block_reduce_max(float v, float* sred) {
    #pragma unroll
    for (int o = 16; o > 0; o >>= 1) v = fmaxf(v, __shfl_xor_sync(0xffffffffu, v, o));
    int wid = threadIdx.x >> 5, lane = threadIdx.x & 31;
    if (lane == 0) sred[wid] = v;
    __syncthreads();
    if (wid == 0) {
        float t = (lane < 8) ? sred[lane] : -1e30f;
        #pragma unroll
        for (int o = 4; o > 0; o >>= 1) t = fmaxf(t, __shfl_xor_sync(0xffffffffu, t, o));
        if (lane == 0) sred[0] = t;
    }
    __syncthreads();
    float r = sred[0];
    __syncthreads();
    return r;
}

// ---------------------------------------------------------------------------
// Kernel 1: fused QKV projection.  out = x @ W + b  for (Wq,Wk,Wv) selected by
// blockIdx.z. NN GEMM, 128x128 block tile, 8x8 micro tile, K-chunk 8.
// M = 8192, N = 1024, K = 1024.
// ---------------------------------------------------------------------------
__global__ __launch_bounds__(256) void qkv_kernel(
    const float* __restrict__ x,
    const float* __restrict__ Wk, const float* __restrict__ bk,
    const float* __restrict__ Wq, const float* __restrict__ bq,
    const float* __restrict__ Wv, const float* __restrict__ bv)
{
    const float* W; const float* bias; float* out;
    if (blockIdx.z == 0)      { W = Wq; bias = bq; out = g_Q; }
    else if (blockIdx.z == 1) { W = Wk; bias = bk; out = g_K; }
    else                      { W = Wv; bias = bv; out = g_V; }

    __shared__ float As[8][128];   // A chunk, transposed (k-major)
    __shared__ float Bs[8][128];   // B chunk, row-major

    const int tid = threadIdx.x;
    const int tx = tid & 15;
    const int ty = tid >> 4;
    const int m0 = blockIdx.y * 128;
    const int n0 = blockIdx.x * 128;

    const int arow = tid >> 1;           // 0..127
    const int acol = (tid & 1) * 4;      // 0 or 4
    const int brow = tid >> 5;           // 0..7
    const int bcol = (tid & 31) * 4;     // 0..124

    float acc[8][8];
    #pragma unroll
    for (int i = 0; i < 8; i++)
        #pragma unroll
        for (int j = 0; j < 8; j++) acc[i][j] = 0.0f;

    const float* Aptr = x + (size_t)(m0 + arow) * DD + acol;
    const float* Bptr = W + (size_t)brow * DD + n0 + bcol;

    for (int k0 = 0; k0 < DD; k0 += 8) {
        float4 av = *(const float4*)(Aptr + k0);
        As[acol + 0][arow] = av.x;
        As[acol + 1][arow] = av.y;
        As[acol + 2][arow] = av.z;
        As[acol + 3][arow] = av.w;
        *(float4*)&Bs[brow][bcol] = *(const float4*)(Bptr + (size_t)k0 * DD);
        __syncthreads();
        #pragma unroll
        for (int t = 0; t < 8; t++) {
            float4 a0 = *(const float4*)&As[t][ty * 4];
            float4 a1 = *(const float4*)&As[t][64 + ty * 4];
            float4 b0 = *(const float4*)&Bs[t][tx * 4];
            float4 b1 = *(const float4*)&Bs[t][64 + tx * 4];
            float af[8] = {a0.x, a0.y, a0.z, a0.w, a1.x, a1.y, a1.z, a1.w};
            float bf[8] = {b0.x, b0.y, b0.z, b0.w, b1.x, b1.y, b1.z, b1.w};
            #pragma unroll
            for (int i = 0; i < 8; i++)
                #pragma unroll
                for (int j = 0; j < 8; j++)
                    acc[i][j] = fmaf(af[i], bf[j], acc[i][j]);
        }
        __syncthreads();
    }

    #pragma unroll
    for (int ih = 0; ih < 2; ih++)
        #pragma unroll
        for (int il = 0; il < 4; il++) {
            int i = ih * 4 + il;
            int m = m0 + ih * 64 + ty * 4 + il;
            float* orow = out + (size_t)m * DD;
            #pragma unroll
            for (int jh = 0; jh < 2; jh++) {
                int n = n0 + jh * 64 + tx * 4;
                float4 o;
                o.x = acc[i][jh * 4 + 0] + bias[n + 0];
                o.y = acc[i][jh * 4 + 1] + bias[n + 1];
                o.z = acc[i][jh * 4 + 2] + bias[n + 2];
                o.w = acc[i][jh * 4 + 3] + bias[n + 3];
                *(float4*)(orow + n) = o;
            }
        }
}

// ---------------------------------------------------------------------------
// Kernel 2: scores = (Q @ K^T) * SCALE, per batch.  NT GEMM.
// M = N = 2048, K = 1024. Output into the "weight" output region (pre-softmax).
// ---------------------------------------------------------------------------
__global__ __launch_bounds__(256) void scores_kernel(float* __restrict__ wgt_all)
{
    const int b = blockIdx.z;
    const float* Q  = g_Q + (size_t)b * SS * DD;
    const float* Kp = g_K + (size_t)b * SS * DD;
    float* C = wgt_all + (size_t)b * SS * SS;

    __shared__ float Qs[8][128];
    __shared__ float Ks[8][128];

    const int tid = threadIdx.x;
    const int tx = tid & 15;
    const int ty = tid >> 4;
    const int m0 = blockIdx.y * 128;
    const int n0 = blockIdx.x * 128;

    const int arow = tid >> 1;
    const int acol = (tid & 1) * 4;

    float acc[8][8];
    #pragma unroll
    for (int i = 0; i < 8; i++)
        #pragma unroll
        for (int j = 0; j < 8; j++) acc[i][j] = 0.0f;

    const float* Qptr = Q  + (size_t)(m0 + arow) * DD + acol;
    const float* Kptr = Kp + (size_t)(n0 + arow) * DD + acol;

    for (int k0 = 0; k0 < DD; k0 += 8) {
        float4 qv = *(const float4*)(Qptr + k0);
        Qs[acol + 0][arow] = qv.x;
        Qs[acol + 1][arow] = qv.y;
        Qs[acol + 2][arow] = qv.z;
        Qs[acol + 3][arow] = qv.w;
        float4 kv = *(const float4*)(Kptr + k0);
        Ks[acol + 0][arow] = kv.x;
        Ks[acol + 1][arow] = kv.y;
        Ks[acol + 2][arow] = kv.z;
        Ks[acol + 3][arow] = kv.w;
        __syncthreads();
        #pragma unroll
        for (int t = 0; t < 8; t++) {
            float4 a0 = *(const float4*)&Qs[t][ty * 4];
            float4 a1 = *(const float4*)&Qs[t][64 + ty * 4];
            float4 b0 = *(const float4*)&Ks[t][tx * 4];
            float4 b1 = *(const float4*)&Ks[t][64 + tx * 4];
            float af[8] = {a0.x, a0.y, a0.z, a0.w, a1.x, a1.y, a1.z, a1.w};
            float bf[8] = {b0.x, b0.y, b0.z, b0.w, b1.x, b1.y, b1.z, b1.w};
            #pragma unroll
            for (int i = 0; i < 8; i++)
                #pragma unroll
                for (int j = 0; j < 8; j++)
                    acc[i][j] = fmaf(af[i], bf[j], acc[i][j]);
        }
        __syncthreads();
    }

    #pragma unroll
    for (int ih = 0; ih < 2; ih++)
        #pragma unroll
        for (int il = 0; il < 4; il++) {
            int i = ih * 4 + il;
            int m = m0 + ih * 64 + ty * 4 + il;
            float* crow = C + (size_t)m * SS;
            #pragma unroll
            for (int jh = 0; jh < 2; jh++) {
                int n = n0 + jh * 64 + tx * 4;
                float4 o;
                o.x = acc[i][jh * 4 + 0] * SCALE;
                o.y = acc[i][jh * 4 + 1] * SCALE;
                o.z = acc[i][jh * 4 + 2] * SCALE;
                o.w = acc[i][jh * 4 + 3] * SCALE;
                *(float4*)(crow + n) = o;
            }
        }
}

// ---------------------------------------------------------------------------
// Kernel 3: row softmax over S=2048, in-place on the weight region.
// One block (256 threads) per row; 8 elements per thread.
// ---------------------------------------------------------------------------
__global__ __launch_bounds__(256) void softmax_kernel(float* __restrict__ w)
{
    float* p = w + (size_t)blockIdx.x * SS;
    const int tid = threadIdx.x;
    __shared__ float sred[8];

    float v[8];
    float m = -1e30f;
    #pragma unroll
    for (int i = 0; i < 8; i++) {
        v[i] = p[tid + i * 256];
        m = fmaxf(m, v[i]);
    }
    m = block_reduce_max(m, sred);

    float s = 0.0f;
    #pragma unroll
    for (int i = 0; i < 8; i++) {
        v[i] = __expf(v[i] - m);
        s += v[i];
    }
    s = block_reduce_sum(s, sred);
    float inv = 1.0f / s;
    #pragma unroll
    for (int i = 0; i < 8; i++) p[tid + i * 256] = v[i] * inv;
}

// ---------------------------------------------------------------------------
// Kernel 4: att = weight @ V, per batch.  NN GEMM.
// M = 2048, N = 1024, K = 2048. Output into the att_score output region.
// ---------------------------------------------------------------------------
__global__ __launch_bounds__(256) void att_kernel(
    const float* __restrict__ wgt_all, float* __restrict__ att)
{
    const int b = blockIdx.z;
    const float* A = wgt_all + (size_t)b * SS * SS;   // lda = SS
    const float* V = g_V + (size_t)b * SS * DD;       // ldb = DD
    float* out = att + (size_t)b * SS * DD;

    __shared__ float As[8][128];
    __shared__ float Bs[8][128];

    const int tid = threadIdx.x;
    const int tx = tid & 15;
    const int ty = tid >> 4;
    const int m0 = blockIdx.y * 128;
    const int n0 = blockIdx.x * 128;

    const int arow = tid >> 1;
    const int acol = (tid & 1) * 4;
    const int brow = tid >> 5;
    const int bcol = (tid & 31) * 4;

    float acc[8][8];
    #pragma unroll
    for (int i = 0; i < 8; i++)
        #pragma unroll
        for (int j = 0; j < 8; j++) acc[i][j] = 0.0f;

    const float* Aptr = A + (size_t)(m0 + arow) * SS + acol;
    const float* Bptr = V + (size_t)brow * DD + n0 + bcol;

    for (int k0 = 0; k0 < SS; k0 += 8) {
        float4 av = *(const float4*)(Aptr + k0);
        As[acol + 0][arow] = av.x;
        As[acol + 1][arow] = av.y;
        As[acol + 2][arow] = av.z;
        As[acol + 3][arow] = av.w;
        *(float4*)&Bs[brow][bcol] = *(const float4*)(Bptr + (size_t)k0 * DD);
        __syncthreads();
        #pragma unroll
        for (int t = 0; t < 8; t++) {
            float4 a0 = *(const float4*)&As[t][ty * 4];
            float4 a1 = *(const float4*)&As[t][64 + ty * 4];
            float4 b0 = *(const float4*)&Bs[t][tx * 4];
            float4 b1 = *(const float4*)&Bs[t][64 + tx * 4];
            float af[8] = {a0.x, a0.y, a0.z, a0.w, a1.x, a1.y, a1.z, a1.w};
            float bf[8] = {b0.x, b0.y, b0.z, b0.w, b1.x, b1.y, b1.z, b1.w};
            #pragma unroll
            for (int i = 0; i < 8; i++)
                #pragma unroll
                for (int j = 0; j < 8; j++)
                    acc[i][j] = fmaf(af[i], bf[j], acc[i][j]);
        }
        __syncthreads();
    }

    #pragma unroll
    for (int ih = 0; ih < 2; ih++)
        #pragma unroll
        for (int il = 0; il < 4; il++) {
            int i = ih * 4 + il;
            int m = m0 + ih * 64 + ty * 4 + il;
            float* orow = out + (size_t)m * DD;
            #pragma unroll
            for (int jh = 0; jh < 2; jh++) {
                int n = n0 + jh * 64 + tx * 4;
                float4 o;
                o.x = acc[i][jh * 4 + 0];
                o.y = acc[i][jh * 4 + 1];
                o.z = acc[i][jh * 4 + 2];
                o.w = acc[i][jh * 4 + 3];
                *(float4*)(orow + n) = o;
            }
        }
}

// ---------------------------------------------------------------------------
// Kernel 5: residual add + LayerNorm.
// out1 = LN(x + att) * gamma + beta.  One block per row of D=1024.
// ---------------------------------------------------------------------------
__global__ __launch_bounds__(256) void ln_kernel(
    const float* __restrict__ x, const float* __restrict__ gamma,
    const float* __restrict__ beta, const float* __restrict__ att,
    float* __restrict__ out1)
{
    const size_t row = blockIdx.x;
    const float* xr = x   + row * DD;
    const float* ar = att + row * DD;
    float* orow = out1 + row * DD;
    const int tid = threadIdx.x;
    __shared__ float sred[8];

    float v[4];
    float s = 0.0f;
    #pragma unroll
    for (int i = 0; i < 4; i++) {
        int c = tid + i * 256;
        v[i] = xr[c] + ar[c];
        s += v[i];
    }
    s = block_reduce_sum(s, sred);
    float mu = s * (1.0f / DD);

    float s2 = 0.0f;
    #pragma unroll
    for (int i = 0; i < 4; i++) {
        float d = v[i] - mu;
        s2 += d * d;
    }
    s2 = block_reduce_sum(s2, sred);
    float rstd = rsqrtf(s2 * (1.0f / DD) + 1e-5f);

    #pragma unroll
    for (int i = 0; i < 4; i++) {
        int c = tid + i * 256;
        orow[c] = (v[i] - mu) * rstd * gamma[c] + beta[c];
    }
}

// ---------------------------------------------------------------------------
// Launch. Inputs (metadata order): x, Wk, bk, Wq, bq, Wv, bv, gamma, beta_ln.
// Output: [out1 (B*S*D) | att_score (B*S*D) | weight (B*S*S)] fp32.
// ---------------------------------------------------------------------------
extern "C" void kernel_launch(void* const* d_in, const int* in_sizes, int n_in,
                              void* d_out, int out_size)
{
    const float* x     = (const float*)d_in[0];
    const float* Wk    = (const float*)d_in[1];
    const float* bk    = (const float*)d_in[2];
    const float* Wq    = (const float*)d_in[3];
    const float* bq    = (const float*)d_in[4];
    const float* Wv    = (const float*)d_in[5];
    const float* bv    = (const float*)d_in[6];
    const float* gamma = (const float*)d_in[7];
    const float* beta  = (const float*)d_in[8];

    float* out  = (float*)d_out;
    float* out1 = out;                                  // [B,S,D]
    float* att  = out + (size_t)BSR * DD;               // [B,S,D]
    float* wgt  = out + (size_t)2 * BSR * DD;           // [B,S,S]

    // 1) QKV projections (3 GEMMs fused by blockIdx.z)
    qkv_kernel<<<dim3(DD / 128, BSR / 128, 3), 256>>>(x, Wk, bk, Wq, bq, Wv, bv);
    // 2) scores = Q K^T * scale -> weight region
    scores_kernel<<<dim3(SS / 128, SS / 128, BB), 256>>>(wgt);
    // 3) softmax in-place
    softmax_kernel<<<BSR, 256>>>(wgt);
    // 4) att = weight @ V
    att_kernel<<<dim3(DD / 128, SS / 128, BB), 256>>>(wgt, att);
    // 5) residual + LayerNorm
    ln_kernel<<<BSR, 256>>>(x, gamma, beta, att, out1);
}

// round 3
// speedup vs baseline: 2.2843x; 2.2843x over previous
#include <cuda_runtime.h>
#include <cuda_bf16.h>
#include <cstdint>
#include <math.h>

#define BB 4
#define SS 2048
#define DD 1024
#define BSR (BB * SS)
#define SCALE (1.0f / 32.0f)

// ---------------------------------------------------------------------------
// Scratch (__device__ globals; no allocation allowed)
// ---------------------------------------------------------------------------
__device__ __align__(128) __nv_bfloat16 g_x_hi[BSR * DD], g_x_lo[BSR * DD];
__device__ __align__(128) __nv_bfloat16 g_Wt_hi[3 * DD * DD], g_Wt_lo[3 * DD * DD];
__device__ __align__(128) __nv_bfloat16 g_Q_hi[BSR * DD], g_Q_lo[BSR * DD];
__device__ __align__(128) __nv_bfloat16 g_K_hi[BSR * DD], g_K_lo[BSR * DD];
__device__ __align__(128) __nv_bfloat16 g_V_hi[BSR * DD], g_V_lo[BSR * DD];
__device__ __align__(128) __nv_bfloat16 g_Vt_hi[(size_t)BB * DD * SS], g_Vt_lo[(size_t)BB * DD * SS];
__device__ __align__(128) __nv_bfloat16 g_w_hi[(size_t)BB * SS * SS], g_w_lo[(size_t)BB * SS * SS];

// ---------------------------------------------------------------------------
// Helpers
// ---------------------------------------------------------------------------
__device__ __forceinline__ uint32_t smem_to_u32(const void* smem_ptr) {
    uint32_t addr;
    asm("{ .reg .u64 tmp; cvta.to.shared.u64 tmp, %1; cvt.u32.u64 %0, tmp; }"
        : "=r"(addr) : "l"(smem_ptr));
    return addr;
}

__device__ __forceinline__ void cga16(uint32_t dst, const void* src) {
    asm volatile("cp.async.cg.shared.global [%0], [%1], 16;" :: "r"(dst), "l"(src));
}
#define CP_COMMIT() asm volatile("cp.async.commit_group;" ::: "memory")
#define CP_WAIT1()  asm volatile("cp.async.wait_group 1;" ::: "memory")

__device__ __forceinline__ void mma16816(float* d, uint32_t a0, uint32_t a1,
                                         uint32_t a2, uint32_t a3,
                                         uint32_t b0, uint32_t b1) {
    asm volatile(
        "mma.sync.aligned.m16n8k16.row.col.f32.bf16.bf16.f32 "
        "{%0,%1,%2,%3}, {%4,%5,%6,%7}, {%8,%9}, {%0,%1,%2,%3};"
        : "+f"(d[0]), "+f"(d[1]), "+f"(d[2]), "+f"(d[3])
        : "r"(a0), "r"(a1), "r"(a2), "r"(a3), "r"(b0), "r"(b1));
}

__device__ __forceinline__ void split2(float v, __nv_bfloat16& h, __nv_bfloat16& l) {
    h = __float2bfloat16_rn(v);
    l = __float2bfloat16_rn(v - __bfloat162float(h));
}

__device__ __forceinline__ uint32_t packbf(__nv_bfloat16 a, __nv_bfloat16 b) {
    __nv_bfloat162 t = __halves2bfloat162(a, b);
    return *reinterpret_cast<uint32_t*>(&t);
}

// ---------------------------------------------------------------------------
// GEMM core: C[128x128] per CTA; 8 warps of 64x32; K-chunk 32; 2-stage cp.async.
// A: [m][k] row-major (lda), B: [n][k] row-major (ldb); hi/lo bf16 split,
// 3-term mma (ah*bh + ah*bl + al*bh).
// SMEM per stage: Ah | Al | Bh | Bl, each 128 rows x 80B (32 bf16 + 16B pad).
// ---------------------------------------------------------------------------
#define TILE_B   10240            // one operand tile
#define STAGE_B  40960            // 4 tiles
#define SMEM_BYTES (2 * STAGE_B)  // 81920

__device__ __forceinline__ void gemm_body(
    float acc[4][4][4],
    const __nv_bfloat16* __restrict__ Ah, const __nv_bfloat16* __restrict__ Al, int lda,
    const __nv_bfloat16* __restrict__ Bh, const __nv_bfloat16* __restrict__ Bl, int ldb,
    int ktot)
{
    extern __shared__ char smem[];
    const uint32_t sb = smem_to_u32(smem);
    const int tid = threadIdx.x;
    const int w = tid >> 5, lane = tid & 31;
    const int wm = (w >> 2) * 64, wn = (w & 3) * 32;
    const int tg = lane >> 2, tig = lane & 3;

    #pragma unroll
    for (int mi = 0; mi < 4; mi++)
        #pragma unroll
        for (int ni = 0; ni < 4; ni++)
            #pragma unroll
            for (int j = 0; j < 4; j++) acc[mi][ni][j] = 0.0f;

    const int id0 = tid, id1 = tid + 256;
    const int r0 = id0 >> 2, c0 = id0 & 3;
    const int r1 = id1 >> 2, c1 = id1 & 3;

    const int nchunks = ktot >> 5;

    // ---- stage loader ----
    auto load_stage = [&](int chunk, int buf) {
        const uint32_t base = sb + buf * STAGE_B;
        const int k0 = chunk << 5;
        {
            uint32_t so = base + r0 * 80 + c0 * 16;
            size_t go = (size_t)r0 * lda + k0 + c0 * 8;
            cga16(so, Ah + go);
            cga16(so + TILE_B, Al + go);
        }
        {
            uint32_t so = base + r1 * 80 + c1 * 16;
            size_t go = (size_t)r1 * lda + k0 + c1 * 8;
            cga16(so, Ah + go);
            cga16(so + TILE_B, Al + go);
        }
        {
            uint32_t so = base + 2 * TILE_B + r0 * 80 + c0 * 16;
            size_t go = (size_t)r0 * ldb + k0 + c0 * 8;
            cga16(so, Bh + go);
            cga16(so + TILE_B, Bl + go);
        }
        {
            uint32_t so = base + 2 * TILE_B + r1 * 80 + c1 * 16;
            size_t go = (size_t)r1 * ldb + k0 + c1 * 8;
            cga16(so, Bh + go);
            cga16(so + TILE_B, Bl + go);
        }
    };

    load_stage(0, 0);
    CP_COMMIT();

    for (int c = 0; c < nchunks; c++) {
        if (c + 1 < nchunks) load_stage(c + 1, (c + 1) & 1);
        CP_COMMIT();
        CP_WAIT1();
        __syncthreads();

        const char* base = smem + (size_t)(c & 1) * STAGE_B;
        #pragma unroll
        for (int ks = 0; ks < 2; ks++) {
            const int kb = (ks * 16 + tig * 2) * 2;   // byte offset of this thread's k pair

            // B fragments (hi+lo) for 4 n-subtiles
            uint32_t bh0[4], bh1[4], bl0[4], bl1[4];
            #pragma unroll
            for (int ni = 0; ni < 4; ni++) {
                const char* pb = base + 2 * TILE_B + (wn + ni * 8 + tg) * 80 + kb;
                bh0[ni] = *(const uint32_t*)(pb);
                bh1[ni] = *(const uint32_t*)(pb + 16);
                bl0[ni] = *(const uint32_t*)(pb + TILE_B);
                bl1[ni] = *(const uint32_t*)(pb + TILE_B + 16);
            }

            #pragma unroll
            for (int mi = 0; mi < 4; mi++) {
                const char* pa = base + (wm + mi * 16 + tg) * 80 + kb;
                uint32_t ah0 = *(const uint32_t*)(pa);
                uint32_t ah1 = *(const uint32_t*)(pa + 8 * 80);
                uint32_t ah2 = *(const uint32_t*)(pa + 16);
                uint32_t ah3 = *(const uint32_t*)(pa + 8 * 80 + 16);
                uint32_t al0 = *(const uint32_t*)(pa + TILE_B);
                uint32_t al1 = *(const uint32_t*)(pa + TILE_B + 8 * 80);
                uint32_t al2 = *(const uint32_t*)(pa + TILE_B + 16);
                uint32_t al3 = *(const uint32_t*)(pa + TILE_B + 8 * 80 + 16);
                #pragma unroll
                for (int ni = 0; ni < 4; ni++) {
                    mma16816(acc[mi][ni], ah0, ah1, ah2, ah3, bh0[ni], bh1[ni]);
                    mma16816(acc[mi][ni], ah0, ah1, ah2, ah3, bl0[ni], bl1[ni]);
                    mma16816(acc[mi][ni], al0, al1, al2, al3, bh0[ni], bh1[ni]);
                }
            }
        }
        __syncthreads();
    }
}

// ---------------------------------------------------------------------------
// GEMM kernels
// ---------------------------------------------------------------------------
__global__ void __launch_bounds__(256, 2) qkv_gemm(
    const float* __restrict__ bq, const float* __restrict__ bk,
    const float* __restrict__ bv)
{
    const int z = blockIdx.z;
    const int m0 = blockIdx.y * 128;
    const int n0 = blockIdx.x * 128;
    const __nv_bfloat16* Bh = g_Wt_hi + (size_t)z * DD * DD + (size_t)n0 * DD;
    const __nv_bfloat16* Bl = g_Wt_lo + (size_t)z * DD * DD + (size_t)n0 * DD;
    const float* bias; __nv_bfloat16 *Oh, *Ol;
    if (z == 0)      { bias = bq; Oh = g_Q_hi; Ol = g_Q_lo; }
    else if (z == 1) { bias = bk; Oh = g_K_hi; Ol = g_K_lo; }
    else             { bias = bv; Oh = g_V_hi; Ol = g_V_lo; }

    float acc[4][4][4];
    gemm_body(acc, g_x_hi + (size_t)m0 * DD, g_x_lo + (size_t)m0 * DD, DD,
              Bh, Bl, DD, DD);

    const int tid = threadIdx.x, w = tid >> 5, lane = tid & 31;
    const int wm = (w >> 2) * 64, wn = (w & 3) * 32;
    const int tg = lane >> 2, tig = lane & 3;
    #pragma unroll
    for (int mi = 0; mi < 4; mi++)
        #pragma unroll
        for (int ni = 0; ni < 4; ni++) {
            int row = m0 + wm + mi * 16 + tg;
            int col = n0 + wn + ni * 8 + tig * 2;
            float b0 = bias[col], b1 = bias[col + 1];
            #pragma unroll
            for (int h = 0; h < 2; h++) {
                float v0 = acc[mi][ni][2 * h]     + b0;
                float v1 = acc[mi][ni][2 * h + 1] + b1;
                __nv_bfloat16 h0, l0, h1, l1;
                split2(v0, h0, l0); split2(v1, h1, l1);
                size_t off = (size_t)(row + 8 * h) * DD + col;
                *(uint32_t*)(Oh + off) = packbf(h0, h1);
                *(uint32_t*)(Ol + off) = packbf(l0, l1);
            }
        }
}

__global__ void __launch_bounds__(256, 2) scores_gemm(float* __restrict__ wgt)
{
    const int b = blockIdx.z;
    const int m0 = blockIdx.y * 128;
    const int n0 = blockIdx.x * 128;
    const size_t abase = ((size_t)b * SS + m0) * DD;
    const size_t bbase = ((size_t)b * SS + n0) * DD;

    float acc[4][4][4];
    gemm_body(acc, g_Q_hi + abase, g_Q_lo + abase, DD,
              g_K_hi + bbase, g_K_lo + bbase, DD, DD);

    float* C = wgt + (size_t)b * SS * SS;
    const int tid = threadIdx.x, w = tid >> 5, lane = tid & 31;
    const int wm = (w >> 2) * 64, wn = (w & 3) * 32;
    const int tg = lane >> 2, tig = lane & 3;
    #pragma unroll
    for (int mi = 0; mi < 4; mi++)
        #pragma unroll
        for (int ni = 0; ni < 4; ni++) {
            int row = m0 + wm + mi * 16 + tg;
            int col = n0 + wn + ni * 8 + tig * 2;
            #pragma unroll
            for (int h = 0; h < 2; h++) {
                float2 v;
                v.x = acc[mi][ni][2 * h]     * SCALE;
                v.y = acc[mi][ni][2 * h + 1] * SCALE;
                *(float2*)&C[(size_t)(row + 8 * h) * SS + col] = v;
            }
        }
}

__global__ void __launch_bounds__(256, 2) att_gemm(float* __restrict__ att)
{
    const int b = blockIdx.z;
    const int m0 = blockIdx.y * 128;
    const int n0 = blockIdx.x * 128;
    const size_t abase = (size_t)b * SS * SS + (size_t)m0 * SS;
    const size_t bbase = ((size_t)b * DD + n0) * SS;

    float acc[4][4][4];
    gemm_body(acc, g_w_hi + abase, g_w_lo + abase, SS,
              g_Vt_hi + bbase, g_Vt_lo + bbase, SS, SS);

    float* C = att + (size_t)b * SS * DD;
    const int tid = threadIdx.x, w = tid >> 5, lane = tid & 31;
    const int wm = (w >> 2) * 64, wn = (w & 3) * 32;
    const int tg = lane >> 2, tig = lane & 3;
    #pragma unroll
    for (int mi = 0; mi < 4; mi++)
        #pragma unroll
        for (int ni = 0; ni < 4; ni++) {
            int row = m0 + wm + mi * 16 + tg;
            int col = n0 + wn + ni * 8 + tig * 2;
            #pragma unroll
            for (int h = 0; h < 2; h++) {
                float2 v;
                v.x = acc[mi][ni][2 * h];
                v.y = acc[mi][ni][2 * h + 1];
                *(float2*)&C[(size_t)(row + 8 * h) * DD + col] = v;
            }
        }
}

// ---------------------------------------------------------------------------
// Conversion / transpose kernels
// ---------------------------------------------------------------------------
__global__ __launch_bounds__(256) void conv_x_kernel(const float* __restrict__ x)
{
    size_t i = (size_t)blockIdx.x * 256 + threadIdx.x;   // over BSR*DD/4
    float4 v = ((const float4*)x)[i];
    __nv_bfloat16 h0, l0, h1, l1, h2, l2, h3, l3;
    split2(v.x, h0, l0); split2(v.y, h1, l1);
    split2(v.z, h2, l2); split2(v.w, h3, l3);
    uint2 uh, ul;
    uh.x = packbf(h0, h1); uh.y = packbf(h2, h3);
    ul.x = packbf(l0, l1); ul.y = packbf(l2, l3);
    ((uint2*)g_x_hi)[i] = uh;
    ((uint2*)g_x_lo)[i] = ul;
}

__global__ __launch_bounds__(256) void wt_kernel(
    const float* __restrict__ Wq, const float* __restrict__ Wk,
    const float* __restrict__ Wv)
{
    const int z = blockIdx.z;
    const float* W = (z == 0) ? Wq : (z == 1) ? Wk : Wv;
    __nv_bfloat16* Oh = g_Wt_hi + (size_t)z * DD * DD;
    __nv_bfloat16* Ol = g_Wt_lo + (size_t)z * DD * DD;
    __shared__ float t[32][33];
    const int tx = threadIdx.x & 31, ty = threadIdx.x >> 5;
    const int x = blockIdx.x * 32 + tx;      // n
    const int y0 = blockIdx.y * 32;          // k
    #pragma unroll
    for (int i = 0; i < 4; i++)
        t[ty + i * 8][tx] = W[(size_t)(y0 + ty + i * 8) * DD + x];
    __syncthreads();
    const int xo = y0 + tx;                  // k out
    const int yo0 = blockIdx.x * 32;         // n out
    #pragma unroll
    for (int i = 0; i < 4; i++) {
        float v = t[tx][ty + i * 8];
        __nv_bfloat16 h, l;
        split2(v, h, l);
        size_t o = (size_t)(yo0 + ty + i * 8) * DD + xo;
        Oh[o] = h; Ol[o] = l;
    }
}

__global__ __launch_bounds__(256) void vt_kernel()
{
    const int b = blockIdx.z;
    __shared__ __nv_bfloat16 th[32][33], tl[32][33];
    const int tx = threadIdx.x & 31, ty = threadIdx.x >> 5;
    const int d0 = blockIdx.x * 32, s0 = blockIdx.y * 32;
    #pragma unroll
    for (int i = 0; i < 4; i++) {
        int s = s0 + ty + i * 8;
        size_t gi = (size_t)(b * SS + s) * DD + d0 + tx;
        th[ty + i * 8][tx] = g_V_hi[gi];
        tl[ty + i * 8][tx] = g_V_lo[gi];
    }
    __syncthreads();
    #pragma unroll
    for (int i = 0; i < 4; i++) {
        int d = d0 + ty + i * 8, s = s0 + tx;
        size_t o = ((size_t)b * DD + d) * SS + s;
        g_Vt_hi[o] = th[tx][ty + i * 8];
        g_Vt_lo[o] = tl[tx][ty + i * 8];
    }
}

// ---------------------------------------------------------------------------
// Reductions + softmax + layernorm
// ---------------------------------------------------------------------------
__device__ __forceinline__ float block_reduce_sum(float v, float* sred) {
    #pragma unroll
    for (int o = 16; o > 0; o >>= 1) v += __shfl_xor_sync(0xffffffffu, v, o);
    int wid = threadIdx.x >> 5, lane = threadIdx.x & 31;
    if (lane == 0) sred[wid] = v;
    __syncthreads();
    if (wid == 0) {
        float t = (lane < 8) ? sred[lane] : 0.0f;
        #pragma unroll
        for (int o = 4; o > 0; o >>= 1) t += __shfl_xor_sync(0xffffffffu, t, o);
        if (lane == 0) sred[0] = t;
    }
    __syncthreads();
    float r = sred[0];
    __syncthreads();
    return r;
}

__device__ __forceinline__ float block_reduce_max(float v, float* sred) {
    #pragma unroll
    for (int o = 16; o > 0; o >>= 1) v = fmaxf(v, __shfl_xor_sync(0xffffffffu, v, o));
    int wid = threadIdx.x >> 5, lane = threadIdx.x & 31;
    if (lane == 0) sred[wid] = v;
    __syncthreads();
    if (wid == 0) {
        float t = (lane < 8) ? sred[lane] : -1e30f;
        #pragma unroll
        for (int o = 4; o > 0; o >>= 1) t = fmaxf(t, __shfl_xor_sync(0xffffffffu, t, o));
        if (lane == 0) sred[0] = t;
    }
    __syncthreads();
    float r = sred[0];
    __syncthreads();
    return r;
}

__global__ __launch_bounds__(256) void softmax_kernel(float* __restrict__ w)
{
    const size_t base = (size_t)blockIdx.x * SS;
    float* p = w + base;
    const int tid = threadIdx.x;
    __shared__ float sred[8];

    float v[8];
    float m = -1e30f;
    #pragma unroll
    for (int i = 0; i < 8; i++) {
        v[i] = p[tid + i * 256];
        m = fmaxf(m, v[i]);
    }
    m = block_reduce_max(m, sred);

    float s = 0.0f;
    #pragma unroll
    for (int i = 0; i < 8; i++) {
        v[i] = __expf(v[i] - m);
        s += v[i];
    }
    s = block_reduce_sum(s, sred);
    float inv = 1.0f / s;
    #pragma unroll
    for (int i = 0; i < 8; i++) {
        int idx = tid + i * 256;
        float wv = v[i] * inv;
        p[idx] = wv;
        __nv_bfloat16 h, l;
        split2(wv, h, l);
        g_w_hi[base + idx] = h;
        g_w_lo[base + idx] = l;
    }
}

__global__ __launch_bounds__(256) void ln_kernel(
    const float* __restrict__ x, const float* __restrict__ gamma,
    const float* __restrict__ beta, const float* __restrict__ att,
    float* __restrict__ out1)
{
    const size_t row = blockIdx.x;
    const float* xr = x   + row * DD;
    const float* ar = att + row * DD;
    float* orow = out1 + row * DD;
    const int tid = threadIdx.x;
    __shared__ float sred[8];

    float v[4];
    float s = 0.0f;
    #pragma unroll
    for (int i = 0; i < 4; i++) {
        int c = tid + i * 256;
        v[i] = xr[c] + ar[c];
        s += v[i];
    }
    s = block_reduce_sum(s, sred);
    float mu = s * (1.0f / DD);

    float s2 = 0.0f;
    #pragma unroll
    for (int i = 0; i < 4; i++) {
        float d = v[i] - mu;
        s2 += d * d;
    }
    s2 = block_reduce_sum(s2, sred);
    float rstd = rsqrtf(s2 * (1.0f / DD) + 1e-5f);

    #pragma unroll
    for (int i = 0; i < 4; i++) {
        int c = tid + i * 256;
        orow[c] = (v[i] - mu) * rstd * gamma[c] + beta[c];
    }
}

// ---------------------------------------------------------------------------
// Launch. Inputs: x, Wk, bk, Wq, bq, Wv, bv, gamma, beta_ln.
// Output: [out1 (B*S*D) | att_score (B*S*D) | weight (B*S*S)] fp32.
// ---------------------------------------------------------------------------
extern "C" void kernel_launch(void* const* d_in, const int* in_sizes, int n_in,
                              void* d_out, int out_size)
{
    const float* x     = (const float*)d_in[0];
    const float* Wk    = (const float*)d_in[1];
    const float* bk    = (const float*)d_in[2];
    const float* Wq    = (const float*)d_in[3];
    const float* bq    = (const float*)d_in[4];
    const float* Wv    = (const float*)d_in[5];
    const float* bv    = (const float*)d_in[6];
    const float* gamma = (const float*)d_in[7];
    const float* beta  = (const float*)d_in[8];

    float* out  = (float*)d_out;
    float* out1 = out;                          // [B,S,D]
    float* att  = out + (size_t)BSR * DD;       // [B,S,D]
    float* wgt  = out + (size_t)2 * BSR * DD;   // [B,S,S]

    cudaFuncSetAttribute(qkv_gemm,    cudaFuncAttributeMaxDynamicSharedMemorySize, SMEM_BYTES);
    cudaFuncSetAttribute(scores_gemm, cudaFuncAttributeMaxDynamicSharedMemorySize, SMEM_BYTES);
    cudaFuncSetAttribute(att_gemm,    cudaFuncAttributeMaxDynamicSharedMemorySize, SMEM_BYTES);

    // 1) fp32 -> bf16 hi/lo conversions
    conv_x_kernel<<<BSR * DD / 4 / 256, 256>>>(x);
    wt_kernel<<<dim3(32, 32, 3), 256>>>(Wq, Wk, Wv);
    // 2) QKV projections (tensor cores)
    qkv_gemm<<<dim3(DD / 128, BSR / 128, 3), 256, SMEM_BYTES>>>(bq, bk, bv);
    // 3) V transpose for the att GEMM B operand
    vt_kernel<<<dim3(DD / 32, SS / 32, BB), 256>>>();
    // 4) scores = Q K^T * scale
    scores_gemm<<<dim3(SS / 128, SS / 128, BB), 256, SMEM_BYTES>>>(wgt);
    // 5) softmax (also emits bf16 hi/lo weight copies)
    softmax_kernel<<<BSR, 256>>>(wgt);
    // 6) att = weight @ V
    att_gemm<<<dim3(DD / 128, SS / 128, BB), 256, SMEM_BYTES>>>(att);
    // 7) residual + LayerNorm
    ln_kernel<<<BSR, 256>>>(x, gamma, beta, att, out1);
}